// round 1
// baseline (speedup 1.0000x reference)
#include <cuda_runtime.h>

// Problem constants (fixed shapes per reference):
//   x0: [8,256,256,64] f32  -> 33,554,432 floats
//   x1: [8,128,128,64] f32  ->  8,388,608 floats
// Output = concat(out0 [8,256,256,64], repl [8,128,128,64], out3 [8,256,256,64])
//        = 75,497,472 floats.
//
// float4-vectorized: N4 = 8*128*128*16 = 2,097,152 threads.

#define N4        2097152
#define OUT0_F4   0          // float4 offset of first output
#define REPL_F4   8388608    // 33,554,432 / 4
#define OUT3_F4   10485760   // + 8,388,608 / 4

// Per-channel "learned-sort unpool" math. v0..v3 = block values (row-major
// within the 2x2 block: (0,0),(0,1),(1,0),(1,1)); p = pooled value.
// Outputs: o* = replaced map, rep = replacement value, q* = fraction map.
__device__ __forceinline__ void lane(
    float v0, float v1, float v2, float v3, float p,
    float& o0, float& o1, float& o2, float& o3,
    float& rep,
    float& q0, float& q1, float& q2, float& q3)
{
    // Value-only descending sort (5-comparator network). Equal values are
    // interchangeable for the cumsum, so no index tracking needed here.
    float a0 = fmaxf(v0, v1), a1 = fminf(v0, v1);
    float a2 = fmaxf(v2, v3), a3 = fminf(v2, v3);
    float s0 = fmaxf(a0, a2), m0 = fminf(a0, a2);
    float s3t = fminf(a1, a3), m1 = fmaxf(a1, a3);
    float s1 = fmaxf(m1, m0), s2 = fminf(m1, m0);
    // sorted descending: s0 >= s1 >= s2 >= s3t

    // Optimal-average scan: avg_j = (sum of top j+1 + p) / (j+2); first max.
    float cs   = s0 + p;
    float best = cs / 2.0f;
    int   k    = 0;
    cs += s1; { float t = cs / 3.0f; if (t > best) { best = t; k = 1; } }
    cs += s2; { float t = cs / 4.0f; if (t > best) { best = t; k = 2; } }
    cs += s3t;{ float t = cs / 5.0f; if (t > best) { best = t; k = 3; } }
    rep = best;

    float frac = (float)(k + 1) / (float)(k + 2);

    // Stable descending rank of each original position:
    // rank_l = #{m : v_m > v_l} + #{m < l : v_m == v_l}
    int r0 = (int)(v1 > v0)  + (int)(v2 > v0)  + (int)(v3 > v0);
    int r1 = (int)(v0 >= v1) + (int)(v2 > v1)  + (int)(v3 > v1);
    int r2 = (int)(v0 >= v2) + (int)(v1 >= v2) + (int)(v3 > v2);
    int r3 = (int)(v0 >= v3) + (int)(v1 >= v3) + (int)(v2 >= v3);

    bool m0b = r0 <= k, m1b = r1 <= k, m2b = r2 <= k, m3b = r3 <= k;
    o0 = m0b ? best : v0;  q0 = m0b ? frac : 1.0f;
    o1 = m1b ? best : v1;  q1 = m1b ? frac : 1.0f;
    o2 = m2b ? best : v2;  q2 = m2b ? frac : 1.0f;
    o3 = m3b ? best : v3;  q3 = m3b ? frac : 1.0f;
}

__global__ void __launch_bounds__(256)
unpool_ls_kernel(const float4* __restrict__ x0,
                 const float4* __restrict__ x1,
                 float4* __restrict__ out)
{
    int idx = blockIdx.x * 256 + threadIdx.x;   // grid covers exactly N4

    // idx decomposition: [b:3][h:7][w:7][c4:4]
    int c4 = idx & 15;
    int t  = idx >> 4;
    int w  = t & 127;
    t >>= 7;
    int h  = t & 127;
    int b  = t >> 7;

    // x0 float4 index of block corner (2h, 2w):
    // ((b*256 + 2h)*256 + 2w)*16 + c4 ; row stride (W*C/4) = 4096 float4.
    int base = ((b * 256 + 2 * h) * 256 + 2 * w) * 16 + c4;

    float4 A = x0[base];            // (2h,   2w)
    float4 Bv = x0[base + 16];      // (2h,   2w+1)
    float4 Cv = x0[base + 4096];    // (2h+1, 2w)
    float4 D = x0[base + 4112];     // (2h+1, 2w+1)
    float4 P = x1[idx];             // pooled

    float4 OA, OB, OC, OD, R, TA, TB, TC, TD;

    lane(A.x, Bv.x, Cv.x, D.x, P.x, OA.x, OB.x, OC.x, OD.x, R.x, TA.x, TB.x, TC.x, TD.x);
    lane(A.y, Bv.y, Cv.y, D.y, P.y, OA.y, OB.y, OC.y, OD.y, R.y, TA.y, TB.y, TC.y, TD.y);
    lane(A.z, Bv.z, Cv.z, D.z, P.z, OA.z, OB.z, OC.z, OD.z, R.z, TA.z, TB.z, TC.z, TD.z);
    lane(A.w, Bv.w, Cv.w, D.w, P.w, OA.w, OB.w, OC.w, OD.w, R.w, TA.w, TB.w, TC.w, TD.w);

    // out0 (same layout as x0)
    out[OUT0_F4 + base]        = OA;
    out[OUT0_F4 + base + 16]   = OB;
    out[OUT0_F4 + base + 4096] = OC;
    out[OUT0_F4 + base + 4112] = OD;

    // repl (pooled layout)
    out[REPL_F4 + idx] = R;

    // out3 (same layout as x0)
    int b3 = OUT3_F4 + base;
    out[b3]        = TA;
    out[b3 + 16]   = TB;
    out[b3 + 4096] = TC;
    out[b3 + 4112] = TD;
}

extern "C" void kernel_launch(void* const* d_in, const int* in_sizes, int n_in,
                              void* d_out, int out_size)
{
    (void)in_sizes; (void)n_in; (void)out_size;
    const float4* x0 = (const float4*)d_in[0];
    const float4* x1 = (const float4*)d_in[1];
    float4* out = (float4*)d_out;

    unpool_ls_kernel<<<N4 / 256, 256>>>(x0, x1, out);
}